// round 4
// baseline (speedup 1.0000x reference)
#include <cuda_runtime.h>
#include <cstdint>
#include <cstdio>

#define TSEQ 512
#define NB   64
#define NI   512
#define NH   1024
#define NHX  1536
#define NG   4096

// ---------------- scratch (no allocation allowed -> device globals) ----------------
__device__ float g_Gx[(size_t)TSEQ * NG * NB];     // [t][gate*NH+u][b]  x-part + bias
__device__ float g_hbuf[2][NH * NB];               // double-buffered hidden state [u][b]
__device__ unsigned g_bar_count;                   // zero-init at module load
__device__ unsigned g_bar_gen;

// ---------------- helpers ----------------
__device__ __forceinline__ unsigned long long lds64(const float* p) {
    return *reinterpret_cast<const unsigned long long*>(p);
}
__device__ __forceinline__ void fma2(unsigned long long& d, unsigned long long a,
                                     unsigned long long b) {
    asm("fma.rn.f32x2 %0, %1, %2, %0;" : "+l"(d) : "l"(a), "l"(b));
}
__device__ __forceinline__ float lo32(unsigned long long v) {
    return __uint_as_float((unsigned)v);
}
__device__ __forceinline__ float hi32(unsigned long long v) {
    return __uint_as_float((unsigned)(v >> 32));
}
__device__ __forceinline__ float sigmoidf_(float v) { return 1.f / (1.f + __expf(-v)); }

// =====================================================================
// Phase 1: Gx[t][g*NH+u][b] = sum_k x[t][b][k] * W[g][u][NH+k] + bias[g][u]
// Per-t GEMM 4096 x 64 x 512. Block tile: 64 rows x 64 batch, K-tile 32.
// f32x2 accumulators over k-pairs (sum halves at the end).
// =====================================================================
__global__ __launch_bounds__(256, 1) void gx_gemm(
    const float* __restrict__ x,
    const float* __restrict__ Wf, const float* __restrict__ Wi,
    const float* __restrict__ Wc, const float* __restrict__ Wo,
    const float* __restrict__ bf, const float* __restrict__ bi,
    const float* __restrict__ bc, const float* __restrict__ bo)
{
    __shared__ float sW[64 * 36];   // [row][k], stride 36 (float4-aligned, bank-safe)
    __shared__ float sX[64 * 34];   // [b][k],  stride 34 (float2-aligned, bank-safe)

    const int t    = blockIdx.y;
    const int jb   = blockIdx.x;          // 0..63 (16 blocks per gate)
    const int gate = jb >> 4;
    const int u0   = (jb & 15) << 6;

    const float* Wsrc = (gate == 0) ? Wf : (gate == 1) ? Wi : (gate == 2) ? Wc : Wo;
    const float* bsrc = (gate == 0) ? bf : (gate == 1) ? bi : (gate == 2) ? bc : bo;

    const int tid  = threadIdx.x;
    const int rg   = tid >> 3;            // 0..31 -> rows {2rg, 2rg+1}
    const int bg   = tid & 7;             // 0..7  -> b in {bg, bg+8, ..., bg+56}
    const int lrow = tid >> 3;            // loader row/batch
    const int kq   = tid & 7;             // loader k quad

    unsigned long long acc[2][8];
#pragma unroll
    for (int r = 0; r < 2; r++)
#pragma unroll
        for (int j = 0; j < 8; j++) acc[r][j] = 0ULL;

    for (int kt = 0; kt < NI; kt += 32) {
#pragma unroll
        for (int p = 0; p < 2; p++) {
            const int r = lrow + p * 32;
            const float4 w4 = *reinterpret_cast<const float4*>(
                Wsrc + (size_t)(u0 + r) * NHX + NH + kt + kq * 4);
            *reinterpret_cast<float4*>(&sW[r * 36 + kq * 4]) = w4;
            const float4 x4 = *reinterpret_cast<const float4*>(
                x + ((size_t)t * NB + r) * NI + kt + kq * 4);
            *reinterpret_cast<float2*>(&sX[r * 34 + kq * 4])     = make_float2(x4.x, x4.y);
            *reinterpret_cast<float2*>(&sX[r * 34 + kq * 4 + 2]) = make_float2(x4.z, x4.w);
        }
        __syncthreads();

#pragma unroll 4
        for (int kp = 0; kp < 16; kp++) {
            unsigned long long wv[2], xv[8];
            wv[0] = lds64(&sW[(rg * 2 + 0) * 36 + 2 * kp]);
            wv[1] = lds64(&sW[(rg * 2 + 1) * 36 + 2 * kp]);
#pragma unroll
            for (int j = 0; j < 8; j++)
                xv[j] = lds64(&sX[(bg + j * 8) * 34 + 2 * kp]);
#pragma unroll
            for (int r = 0; r < 2; r++)
#pragma unroll
                for (int j = 0; j < 8; j++)
                    fma2(acc[r][j], wv[r], xv[j]);
        }
        __syncthreads();
    }

#pragma unroll
    for (int r = 0; r < 2; r++) {
        const int row  = rg * 2 + r;
        const float bias = bsrc[u0 + row];
        float* Cp = g_Gx + ((size_t)t * NG + (size_t)gate * NH + u0 + row) * NB;
#pragma unroll
        for (int j = 0; j < 8; j++)
            Cp[bg + j * 8] = lo32(acc[r][j]) + hi32(acc[r][j]) + bias;
    }
}

// =====================================================================
// Phase 2: persistent recurrent kernel.
// 128 CTAs x 256 threads. CTA owns units [8*cta, 8*cta+8): 32 weight rows
// (4 gates x 8 units x 1024) resident in SMEM for all 512 steps.
// One grid barrier per step (h double-buffered -> no WAR hazard).
// =====================================================================
#define SW_STRIDE 1032
#define SH_STRIDE 130
#define SG_STRIDE 66
#define P2_SMEM ((32 * SW_STRIDE + NB * SH_STRIDE + 32 * SG_STRIDE) * 4)  // 173824 B

__device__ __forceinline__ void grid_barrier() {
    __threadfence();                 // publish my stores (incl. __stcg h writes)
    __syncthreads();
    if (threadIdx.x == 0) {
        volatile unsigned* vgen = &g_bar_gen;
        const unsigned gen = *vgen;                    // stable: this round can't
        const unsigned arrived = atomicAdd(&g_bar_count, 1u);  // finish without me
        if ((arrived & 127u) == 127u) {                // 128 divides 2^32: wrap-safe
            atomicAdd(&g_bar_gen, 1u);
        } else {
            while (*vgen == gen) { }
        }
    }
    __syncthreads();
    __threadfence();
}

__global__ __launch_bounds__(256, 1) void lstm_steps(
    const float* __restrict__ Wf, const float* __restrict__ Wi,
    const float* __restrict__ Wc, const float* __restrict__ Wo,
    float* __restrict__ out)
{
    extern __shared__ float smem[];
    float* sW = smem;                      // 32 x 1032
    float* sH = sW + 32 * SW_STRIDE;       // 64 x 130   h tile, [b][k]
    float* sG = sH + NB * SH_STRIDE;       // 32 x 66    staged gate pre-acts

    const int tid    = threadIdx.x;
    const int u_base = blockIdx.x * 8;

    // Load this CTA's 32 weight rows (h-part = columns [0, NH)) into SMEM once.
    for (int i = tid; i < 8192; i += 256) {       // 8192 float4s = 32 rows x 1024
        const int r = i >> 8, q = i & 255;
        const int g = r >> 3, ul = r & 7;
        const float* Wsrc = (g == 0) ? Wf : (g == 1) ? Wi : (g == 2) ? Wc : Wo;
        const float4 v = *reinterpret_cast<const float4*>(
            Wsrc + (size_t)(u_base + ul) * NHX + q * 4);
        *reinterpret_cast<float4*>(&sW[r * SW_STRIDE + q * 4]) = v;
    }
    // Zero h buffer 0 for owned units (h_{-1} = 0).
    for (int i = tid; i < 8 * NB; i += 256)
        g_hbuf[0][u_base * NB + i] = 0.f;

    // dot-phase mapping: rows {2ty,2ty+1}, batches {tx, tx+16, tx+32, tx+48}
    const int ty = tid >> 4;
    const int tx = tid & 15;
    // combine mapping: unit u_l, batch pair (2bp, 2bp+1); c lives in registers
    const int u_l = tid >> 5;
    const int bp  = tid & 31;
    const int b0  = bp * 2;
    float2 creg = make_float2(0.f, 0.f);

    grid_barrier();   // h0 zeros visible everywhere

    for (int t = 0; t < TSEQ; t++) {
        const float* hprev = g_hbuf[t & 1];
        float* hnext = g_hbuf[(t & 1) ^ 1];

        unsigned long long acc[2][4];
#pragma unroll
        for (int r = 0; r < 2; r++)
#pragma unroll
            for (int j = 0; j < 4; j++) acc[r][j] = 0ULL;

        for (int kt = 0; kt < NH; kt += 128) {
            // load + transpose h tile: global [k][b] -> smem [b][k]
#pragma unroll
            for (int p = 0; p < 8; p++) {
                const int idx = tid + p * 256;          // float4 index, 0..2047
                const int kk = idx >> 4;
                const int bb = (idx & 15) * 4;
                const float4 v = __ldcg(reinterpret_cast<const float4*>(
                    hprev + (size_t)(kt + kk) * NB + bb));
                sH[(bb + 0) * SH_STRIDE + kk] = v.x;
                sH[(bb + 1) * SH_STRIDE + kk] = v.y;
                sH[(bb + 2) * SH_STRIDE + kk] = v.z;
                sH[(bb + 3) * SH_STRIDE + kk] = v.w;
            }
            __syncthreads();

            const float* w0 = sW + (ty * 2) * SW_STRIDE + kt;
            const float* w1 = w0 + SW_STRIDE;
            const float* h0 = sH + tx * SH_STRIDE;
            const float* h1 = sH + (tx + 16) * SH_STRIDE;
            const float* h2 = sH + (tx + 32) * SH_STRIDE;
            const float* h3 = sH + (tx + 48) * SH_STRIDE;
#pragma unroll 8
            for (int kp = 0; kp < 64; kp++) {
                const unsigned long long wv0 = lds64(w0 + 2 * kp);
                const unsigned long long wv1 = lds64(w1 + 2 * kp);
                const unsigned long long hv0 = lds64(h0 + 2 * kp);
                const unsigned long long hv1 = lds64(h1 + 2 * kp);
                const unsigned long long hv2 = lds64(h2 + 2 * kp);
                const unsigned long long hv3 = lds64(h3 + 2 * kp);
                fma2(acc[0][0], wv0, hv0);
                fma2(acc[0][1], wv0, hv1);
                fma2(acc[0][2], wv0, hv2);
                fma2(acc[0][3], wv0, hv3);
                fma2(acc[1][0], wv1, hv0);
                fma2(acc[1][1], wv1, hv1);
                fma2(acc[1][2], wv1, hv2);
                fma2(acc[1][3], wv1, hv3);
            }
            __syncthreads();
        }

        // stage h-part gate pre-activations in SMEM
#pragma unroll
        for (int r = 0; r < 2; r++)
#pragma unroll
            for (int j = 0; j < 4; j++)
                sG[(ty * 2 + r) * SG_STRIDE + (tx + j * 16)] =
                    lo32(acc[r][j]) + hi32(acc[r][j]);
        __syncthreads();

        // combine: gates -> c, h; write h to double buffer + output
        {
            const int u = u_base + u_l;
            const float* Gp = g_Gx + (size_t)t * NG * NB;
            const float2 hf = *reinterpret_cast<const float2*>(&sG[(0  + u_l) * SG_STRIDE + b0]);
            const float2 hi = *reinterpret_cast<const float2*>(&sG[(8  + u_l) * SG_STRIDE + b0]);
            const float2 hc = *reinterpret_cast<const float2*>(&sG[(16 + u_l) * SG_STRIDE + b0]);
            const float2 ho = *reinterpret_cast<const float2*>(&sG[(24 + u_l) * SG_STRIDE + b0]);
            const float2 xf = *reinterpret_cast<const float2*>(Gp + ((size_t)0 * NH + u) * NB + b0);
            const float2 xi = *reinterpret_cast<const float2*>(Gp + ((size_t)1 * NH + u) * NB + b0);
            const float2 xc = *reinterpret_cast<const float2*>(Gp + ((size_t)2 * NH + u) * NB + b0);
            const float2 xo = *reinterpret_cast<const float2*>(Gp + ((size_t)3 * NH + u) * NB + b0);

            const float fx = sigmoidf_(hf.x + xf.x), fy = sigmoidf_(hf.y + xf.y);
            const float ix = sigmoidf_(hi.x + xi.x), iy = sigmoidf_(hi.y + xi.y);
            const float cx = tanhf(hc.x + xc.x),     cy = tanhf(hc.y + xc.y);
            const float ox = sigmoidf_(ho.x + xo.x), oy = sigmoidf_(ho.y + xo.y);

            creg.x = fx * creg.x + ix * cx;
            creg.y = fy * creg.y + iy * cy;
            const float hx_ = ox * tanhf(creg.x);
            const float hy_ = oy * tanhf(creg.y);

            __stcg(reinterpret_cast<float2*>(hnext + (size_t)u * NB + b0),
                   make_float2(hx_, hy_));
            out[((size_t)t * NB + b0) * NH + u]     = hx_;
            out[((size_t)t * NB + b0 + 1) * NH + u] = hy_;
        }

        grid_barrier();   // h_t visible before anyone reads it at t+1
    }
}

// =====================================================================
// launch
// =====================================================================
extern "C" void kernel_launch(void* const* d_in, const int* in_sizes, int n_in,
                              void* d_out, int out_size)
{
    const float* x  = (const float*)d_in[0];
    const float* Wf = (const float*)d_in[1];
    const float* bf = (const float*)d_in[2];
    const float* Wi = (const float*)d_in[3];
    const float* bi = (const float*)d_in[4];
    const float* Wc = (const float*)d_in[5];
    const float* bc = (const float*)d_in[6];
    const float* Wo = (const float*)d_in[7];
    const float* bo = (const float*)d_in[8];
    float* out = (float*)d_out;

    (void)in_sizes; (void)n_in; (void)out_size;

    cudaFuncSetAttribute(lstm_steps, cudaFuncAttributeMaxDynamicSharedMemorySize, P2_SMEM);

    gx_gemm<<<dim3(64, TSEQ), 256>>>(x, Wf, Wi, Wc, Wo, bf, bi, bc, bo);
    lstm_steps<<<128, 256, P2_SMEM>>>(Wf, Wi, Wc, Wo, out);
}

// round 6
// speedup vs baseline: 1.1521x; 1.1521x over previous
#include <cuda_runtime.h>
#include <cstdint>
#include <cstdio>

#define TSEQ 512
#define NB   64
#define NI   512
#define NH   1024
#define NHX  1536
#define NG   4096

// ---------------- scratch (no allocation allowed -> device globals) ----------------
__device__ float g_Gx[(size_t)TSEQ * NG * NB];     // [t][gate*NH+u][b]  x-part + bias
__device__ float g_hbuf[2][NH * NB];               // double-buffered hidden state [u][b]
__device__ unsigned g_bar_count;                   // zero-init at module load
__device__ unsigned g_bar_gen;

// ---------------- helpers ----------------
__device__ __forceinline__ unsigned long long lds64(const float* p) {
    return *reinterpret_cast<const unsigned long long*>(p);
}
__device__ __forceinline__ void fma2(unsigned long long& d, unsigned long long a,
                                     unsigned long long b) {
    asm("fma.rn.f32x2 %0, %1, %2, %0;" : "+l"(d) : "l"(a), "l"(b));
}
__device__ __forceinline__ float lo32(unsigned long long v) {
    return __uint_as_float((unsigned)v);
}
__device__ __forceinline__ float hi32(unsigned long long v) {
    return __uint_as_float((unsigned)(v >> 32));
}
__device__ __forceinline__ float sigmoidf_(float v) { return 1.f / (1.f + __expf(-v)); }

// =====================================================================
// Phase 1: Gx[t][g*NH+u][b] = sum_k x[t][b][k] * W[g][u][NH+k] + bias
// Per-t GEMM 4096 x 64 x 512. Block tile: 64 rows x 64 batch, K-tile 32.
// Register tile 8x8 per thread, 2-way K-split (kc = tid&1), shfl reduce.
// 16 LDS.64 feed 64 FFMA2 per k-pair -> 0.25 LDS/FMA2 (was 0.625).
// =====================================================================
__global__ __launch_bounds__(128, 2) void gx_gemm(
    const float* __restrict__ x,
    const float* __restrict__ Wf, const float* __restrict__ Wi,
    const float* __restrict__ Wc, const float* __restrict__ Wo,
    const float* __restrict__ bf, const float* __restrict__ bi,
    const float* __restrict__ bc, const float* __restrict__ bo)
{
    __shared__ float sW[64 * 36];   // [row][k], stride 36
    __shared__ float sX[64 * 34];   // [b][k],  stride 34

    const int t    = blockIdx.y;
    const int jb   = blockIdx.x;          // 0..63 (16 blocks per gate)
    const int gate = jb >> 4;
    const int u0   = (jb & 15) << 6;

    const float* Wsrc = (gate == 0) ? Wf : (gate == 1) ? Wi : (gate == 2) ? Wc : Wo;
    const float* bsrc = (gate == 0) ? bf : (gate == 1) ? bi : (gate == 2) ? bc : bo;

    const int tid = threadIdx.x;          // 0..127
    const int kc  = tid & 1;              // K split (2 chunks, strided k-pairs)
    const int pos = tid >> 1;             // 0..63
    const int bg  = pos & 7;              // batches bg*8 .. bg*8+7
    const int rg  = pos >> 3;             // rows rg*8 .. rg*8+7

    unsigned long long acc[8][8];
#pragma unroll
    for (int i = 0; i < 8; i++)
#pragma unroll
        for (int j = 0; j < 8; j++) acc[i][j] = 0ULL;

    for (int kt = 0; kt < NI; kt += 32) {
        // stage tile: 64 rows x 32 k of W, 64 b x 32 k of x (512 float4 each)
#pragma unroll
        for (int p = 0; p < 4; p++) {
            const int idx = tid + p * 128;        // 0..511
            const int r = idx >> 3, q = idx & 7;
            const float4 w4 = *reinterpret_cast<const float4*>(
                Wsrc + (size_t)(u0 + r) * NHX + NH + kt + q * 4);
            *reinterpret_cast<float4*>(&sW[r * 36 + q * 4]) = w4;
            const float4 x4 = *reinterpret_cast<const float4*>(
                x + ((size_t)t * NB + r) * NI + kt + q * 4);
            *reinterpret_cast<float2*>(&sX[r * 34 + q * 4])     = make_float2(x4.x, x4.y);
            *reinterpret_cast<float2*>(&sX[r * 34 + q * 4 + 2]) = make_float2(x4.z, x4.w);
        }
        __syncthreads();

        const float* wb = sW + rg * 8 * 36 + 2 * kc;
        const float* xb = sX + bg * 8 * 34 + 2 * kc;
#pragma unroll 2
        for (int j = 0; j < 8; j++) {         // k-pair = 2j + kc
            unsigned long long wv[8], xv[8];
#pragma unroll
            for (int i = 0; i < 8; i++) wv[i] = lds64(wb + i * 36 + 4 * j);
#pragma unroll
            for (int jj = 0; jj < 8; jj++) xv[jj] = lds64(xb + jj * 34 + 4 * j);
#pragma unroll
            for (int i = 0; i < 8; i++)
#pragma unroll
                for (int jj = 0; jj < 8; jj++)
                    fma2(acc[i][jj], wv[i], xv[jj]);
        }
        __syncthreads();
    }

    // reduce halves + 1-round butterfly over kc (lane bit 0)
    float s[8][8];
#pragma unroll
    for (int i = 0; i < 8; i++)
#pragma unroll
        for (int jj = 0; jj < 8; jj++) {
            float v = lo32(acc[i][jj]) + hi32(acc[i][jj]);
            v += __shfl_xor_sync(0xffffffffu, v, 1);
            s[i][jj] = v;
        }

    // thread kc writes rows with i%2==kc (static indexing)
#pragma unroll
    for (int i = 0; i < 8; i++) {
        if ((i & 1) == kc) {
            const int row = rg * 8 + i;
            const float bias = bsrc[u0 + row];
            float* Cp = g_Gx + ((size_t)t * NG + (size_t)gate * NH + u0 + row) * NB + bg * 8;
            *reinterpret_cast<float4*>(Cp) =
                make_float4(s[i][0] + bias, s[i][1] + bias, s[i][2] + bias, s[i][3] + bias);
            *reinterpret_cast<float4*>(Cp + 4) =
                make_float4(s[i][4] + bias, s[i][5] + bias, s[i][6] + bias, s[i][7] + bias);
        }
    }
}

// =====================================================================
// Phase 2: persistent recurrent kernel.
// 128 CTAs x 256 threads. CTA owns 32 weight rows (4 gates x 8 units),
// resident in SMEM all 512 steps. Register tile 8x8 per thread with
// 8-way K-split (kc = tid&7) + 3-round shfl butterfly reduction.
// 16 LDS.64 feed 64 FFMA2 per k-pair -> 0.25 LDS/FMA2 (was 0.75).
// =====================================================================
#define SW_STRIDE 1032
#define SH_STRIDE 130
#define SG_STRIDE 68
#define P2_SMEM ((32 * SW_STRIDE + NB * SH_STRIDE + 32 * SG_STRIDE) * 4)  // 174080 B

__device__ __forceinline__ void grid_barrier() {
    __threadfence();
    __syncthreads();
    if (threadIdx.x == 0) {
        volatile unsigned* vgen = &g_bar_gen;
        const unsigned gen = *vgen;
        const unsigned arrived = atomicAdd(&g_bar_count, 1u);
        if ((arrived & 127u) == 127u) {
            atomicAdd(&g_bar_gen, 1u);
        } else {
            while (*vgen == gen) { }
        }
    }
    __syncthreads();
    __threadfence();
}

__global__ __launch_bounds__(256, 1) void lstm_steps(
    const float* __restrict__ Wf, const float* __restrict__ Wi,
    const float* __restrict__ Wc, const float* __restrict__ Wo,
    float* __restrict__ out)
{
    extern __shared__ float smem[];
    float* sW = smem;                      // 32 x 1032   weights, whole kernel
    float* sH = sW + 32 * SW_STRIDE;       // 64 x 130    h tile [b][k]
    float* sG = sH + NB * SH_STRIDE;       // 32 x 68     staged gate pre-acts

    const int tid    = threadIdx.x;
    const int u_base = blockIdx.x * 8;

    // Load this CTA's 32 weight rows (h-part = cols [0, NH)) into SMEM once.
    for (int i = tid; i < 8192; i += 256) {       // 8192 float4s
        const int r = i >> 8, q = i & 255;
        const int g = r >> 3, ul = r & 7;
        const float* Wsrc = (g == 0) ? Wf : (g == 1) ? Wi : (g == 2) ? Wc : Wo;
        const float4 v = *reinterpret_cast<const float4*>(
            Wsrc + (size_t)(u_base + ul) * NHX + q * 4);
        *reinterpret_cast<float4*>(&sW[r * SW_STRIDE + q * 4]) = v;
    }
    // Zero h buffer 0 for owned units (h_{-1} = 0).
    for (int i = tid; i < 8 * NB; i += 256)
        g_hbuf[0][u_base * NB + i] = 0.f;

    // dot-phase mapping: kc = K split slot, rg = gate, bg = batch octet
    const int kc  = tid & 7;
    const int pos = tid >> 3;              // 0..31
    const int bg  = pos & 7;               // batches bg*8 .. bg*8+7
    const int rg  = pos >> 3;              // rows rg*8 .. rg*8+7 (rg == gate)
    // combine mapping: unit u_l, batch pair (2bp, 2bp+1); c in registers
    const int u_l = tid >> 5;
    const int bp  = tid & 31;
    const int b0  = bp * 2;
    float2 creg = make_float2(0.f, 0.f);

    grid_barrier();   // h0 zeros visible everywhere

    for (int t = 0; t < TSEQ; t++) {
        const float* hprev = g_hbuf[t & 1];
        float* hnext = g_hbuf[(t & 1) ^ 1];

        unsigned long long acc[8][8];
#pragma unroll
        for (int i = 0; i < 8; i++)
#pragma unroll
            for (int j = 0; j < 8; j++) acc[i][j] = 0ULL;

        for (int kt = 0; kt < NH; kt += 128) {
            // load + transpose h tile: global [k][b] -> smem [b][k]
#pragma unroll
            for (int p = 0; p < 8; p++) {
                const int idx = tid + p * 256;          // float4 index, 0..2047
                const int kk = idx >> 4;
                const int bb = (idx & 15) * 4;
                const float4 v = __ldcg(reinterpret_cast<const float4*>(
                    hprev + (size_t)(kt + kk) * NB + bb));
                sH[(bb + 0) * SH_STRIDE + kk] = v.x;
                sH[(bb + 1) * SH_STRIDE + kk] = v.y;
                sH[(bb + 2) * SH_STRIDE + kk] = v.z;
                sH[(bb + 3) * SH_STRIDE + kk] = v.w;
            }
            __syncthreads();

            const float* wb = sW + rg * 8 * SW_STRIDE + kt + 2 * kc;
            const float* hb = sH + bg * 8 * SH_STRIDE + 2 * kc;
#pragma unroll 2
            for (int j = 0; j < 8; j++) {        // k-pair = 8j + kc
                unsigned long long wv[8], hv[8];
#pragma unroll
                for (int i = 0; i < 8; i++) wv[i] = lds64(wb + i * SW_STRIDE + 16 * j);
#pragma unroll
                for (int jj = 0; jj < 8; jj++) hv[jj] = lds64(hb + jj * SH_STRIDE + 16 * j);
#pragma unroll
                for (int i = 0; i < 8; i++)
#pragma unroll
                    for (int jj = 0; jj < 8; jj++)
                        fma2(acc[i][jj], wv[i], hv[jj]);
            }
            __syncthreads();
        }

        // reduce halves + 3-round butterfly over kc (lane bits 0..2)
        float s[8][8];
#pragma unroll
        for (int i = 0; i < 8; i++)
#pragma unroll
            for (int jj = 0; jj < 8; jj++) {
                float v = lo32(acc[i][jj]) + hi32(acc[i][jj]);
                v += __shfl_xor_sync(0xffffffffu, v, 1);
                v += __shfl_xor_sync(0xffffffffu, v, 2);
                v += __shfl_xor_sync(0xffffffffu, v, 4);
                s[i][jj] = v;
            }

        // thread kc writes its row (i == kc): static indexing, 2x STS.128
#pragma unroll
        for (int i = 0; i < 8; i++) {
            if (i == kc) {
                float* Gr = &sG[(rg * 8 + i) * SG_STRIDE + bg * 8];
                *reinterpret_cast<float4*>(Gr) =
                    make_float4(s[i][0], s[i][1], s[i][2], s[i][3]);
                *reinterpret_cast<float4*>(Gr + 4) =
                    make_float4(s[i][4], s[i][5], s[i][6], s[i][7]);
            }
        }
        __syncthreads();

        // combine: gates -> c, h; write h to double buffer + output
        {
            const int u = u_base + u_l;
            const float* Gp = g_Gx + (size_t)t * NG * NB;
            const float2 hf = *reinterpret_cast<const float2*>(&sG[(0  + u_l) * SG_STRIDE + b0]);
            const float2 hi = *reinterpret_cast<const float2*>(&sG[(8  + u_l) * SG_STRIDE + b0]);
            const float2 hc = *reinterpret_cast<const float2*>(&sG[(16 + u_l) * SG_STRIDE + b0]);
            const float2 ho = *reinterpret_cast<const float2*>(&sG[(24 + u_l) * SG_STRIDE + b0]);
            const float2 xf = *reinterpret_cast<const float2*>(Gp + ((size_t)0 * NH + u) * NB + b0);
            const float2 xi = *reinterpret_cast<const float2*>(Gp + ((size_t)1 * NH + u) * NB + b0);
            const float2 xc = *reinterpret_cast<const float2*>(Gp + ((size_t)2 * NH + u) * NB + b0);
            const float2 xo = *reinterpret_cast<const float2*>(Gp + ((size_t)3 * NH + u) * NB + b0);

            const float fx = sigmoidf_(hf.x + xf.x), fy = sigmoidf_(hf.y + xf.y);
            const float ix = sigmoidf_(hi.x + xi.x), iy = sigmoidf_(hi.y + xi.y);
            const float cx = tanhf(hc.x + xc.x),     cy = tanhf(hc.y + xc.y);
            const float ox = sigmoidf_(ho.x + xo.x), oy = sigmoidf_(ho.y + xo.y);

            creg.x = fx * creg.x + ix * cx;
            creg.y = fy * creg.y + iy * cy;
            const float hx_ = ox * tanhf(creg.x);
            const float hy_ = oy * tanhf(creg.y);

            __stcg(reinterpret_cast<float2*>(hnext + (size_t)u * NB + b0),
                   make_float2(hx_, hy_));
            out[((size_t)t * NB + b0) * NH + u]     = hx_;
            out[((size_t)t * NB + b0 + 1) * NH + u] = hy_;
        }

        grid_barrier();   // h_t visible before anyone reads it at t+1
    }
}

// =====================================================================
// launch
// =====================================================================
extern "C" void kernel_launch(void* const* d_in, const int* in_sizes, int n_in,
                              void* d_out, int out_size)
{
    const float* x  = (const float*)d_in[0];
    const float* Wf = (const float*)d_in[1];
    const float* bf = (const float*)d_in[2];
    const float* Wi = (const float*)d_in[3];
    const float* bi = (const float*)d_in[4];
    const float* Wc = (const float*)d_in[5];
    const float* bc = (const float*)d_in[6];
    const float* Wo = (const float*)d_in[7];
    const float* bo = (const float*)d_in[8];
    float* out = (float*)d_out;

    (void)in_sizes; (void)n_in; (void)out_size;

    cudaFuncSetAttribute(lstm_steps, cudaFuncAttributeMaxDynamicSharedMemorySize, P2_SMEM);

    gx_gemm<<<dim3(64, TSEQ), 128>>>(x, Wf, Wi, Wc, Wo, bf, bi, bc, bo);
    lstm_steps<<<128, 256, P2_SMEM>>>(Wf, Wi, Wc, Wo, out);
}

// round 10
// speedup vs baseline: 1.5553x; 1.3500x over previous
#include <cuda_runtime.h>
#include <cstdint>
#include <cstdio>

#define TSEQ 512
#define NB   64
#define NI   512
#define NH   1024
#define NHX  1536
#define NG   4096

// ---------------- scratch (no allocation allowed -> device globals) ----------------
__device__ float g_Gx[(size_t)TSEQ * NG * NB];     // [t][gate*NH+u][b]  x-part + bias
__device__ float g_hbuf[2][NB * NH];               // double-buffered hidden state [b][k]
__device__ unsigned g_bar_count;                   // zero-init at module load
__device__ unsigned g_bar_gen;

// ---------------- helpers ----------------
__device__ __forceinline__ unsigned long long lds64(const float* p) {
    return *reinterpret_cast<const unsigned long long*>(p);
}
__device__ __forceinline__ void fma2(unsigned long long& d, unsigned long long a,
                                     unsigned long long b) {
    asm("fma.rn.f32x2 %0, %1, %2, %0;" : "+l"(d) : "l"(a), "l"(b));
}
__device__ __forceinline__ float lo32(unsigned long long v) {
    return __uint_as_float((unsigned)v);
}
__device__ __forceinline__ float hi32(unsigned long long v) {
    return __uint_as_float((unsigned)(v >> 32));
}
__device__ __forceinline__ float sigmoidf_(float v) { return 1.f / (1.f + __expf(-v)); }

// =====================================================================
// Phase 1: Gx[t][g*NH+u][b] = sum_k x[t][b][k] * W[g][u][NH+k] + bias
// Per-t GEMM 4096 x 64 x 512. 64x64 block tile, K-tile 32, 8x8 regs,
// 2-way K-split. Strided-b (b = bg + 8*jj) + stride-36 sX: compute reads
// conflict-free (banks 4*bg + 2*kc all distinct). Register-double-
// buffered staging hides LDG latency.
// =====================================================================
__global__ __launch_bounds__(128, 2) void gx_gemm(
    const float* __restrict__ x,
    const float* __restrict__ Wf, const float* __restrict__ Wi,
    const float* __restrict__ Wc, const float* __restrict__ Wo,
    const float* __restrict__ bf, const float* __restrict__ bi,
    const float* __restrict__ bc, const float* __restrict__ bo)
{
    __shared__ float sW[64 * 36];   // [row][k]
    __shared__ float sX[64 * 36];   // [b][k]

    const int t    = blockIdx.y;
    const int jb   = blockIdx.x;          // 0..63 (16 blocks per gate)
    const int gate = jb >> 4;
    const int u0   = (jb & 15) << 6;

    const float* Wsrc = (gate == 0) ? Wf : (gate == 1) ? Wi : (gate == 2) ? Wc : Wo;
    const float* bsrc = (gate == 0) ? bf : (gate == 1) ? bi : (gate == 2) ? bc : bo;

    const int tid = threadIdx.x;          // 0..127
    const int kc  = tid & 1;              // K split
    const int bg  = (tid >> 1) & 7;       // b in {bg, bg+8, ..., bg+56}
    const int rg  = tid >> 4;             // rows rg*8 .. rg*8+7

    const int lr = tid >> 3;              // loader row/batch
    const int lq = tid & 7;               // loader k-quad

    unsigned long long acc[8][8];
#pragma unroll
    for (int i = 0; i < 8; i++)
#pragma unroll
        for (int j = 0; j < 8; j++) acc[i][j] = 0ULL;

    float4 wreg[4], xreg[4];
    // preload tile 0 into registers
#pragma unroll
    for (int p = 0; p < 4; p++) {
        const int r = lr + p * 16;
        wreg[p] = *reinterpret_cast<const float4*>(
            Wsrc + (size_t)(u0 + r) * NHX + NH + lq * 4);
        xreg[p] = *reinterpret_cast<const float4*>(
            x + ((size_t)t * NB + r) * NI + lq * 4);
    }

    for (int kt = 0; kt < NI; kt += 32) {
        __syncthreads();   // previous compute done -> safe to overwrite
#pragma unroll
        for (int p = 0; p < 4; p++) {
            const int r = lr + p * 16;
            *reinterpret_cast<float4*>(&sW[r * 36 + lq * 4]) = wreg[p];
            *reinterpret_cast<float2*>(&sX[r * 36 + lq * 4]) = make_float2(xreg[p].x, xreg[p].y);
            *reinterpret_cast<float2*>(&sX[r * 36 + lq * 4 + 2]) = make_float2(xreg[p].z, xreg[p].w);
        }
        __syncthreads();   // tile visible
        if (kt + 32 < NI) {
#pragma unroll
            for (int p = 0; p < 4; p++) {
                const int r = lr + p * 16;
                wreg[p] = *reinterpret_cast<const float4*>(
                    Wsrc + (size_t)(u0 + r) * NHX + NH + kt + 32 + lq * 4);
                xreg[p] = *reinterpret_cast<const float4*>(
                    x + ((size_t)t * NB + r) * NI + kt + 32 + lq * 4);
            }
        }

#pragma unroll 2
        for (int j = 0; j < 8; j++) {         // k-pair = 2j + kc
            unsigned long long wv[8], xv[8];
#pragma unroll
            for (int i = 0; i < 8; i++)
                wv[i] = lds64(&sW[(rg * 8 + i) * 36 + 4 * j + 2 * kc]);
#pragma unroll
            for (int jj = 0; jj < 8; jj++)
                xv[jj] = lds64(&sX[(bg + 8 * jj) * 36 + 4 * j + 2 * kc]);
#pragma unroll
            for (int i = 0; i < 8; i++)
#pragma unroll
                for (int jj = 0; jj < 8; jj++)
                    fma2(acc[i][jj], wv[i], xv[jj]);
        }
    }

    // reduce halves + 1-round butterfly over kc (lane bit 0)
    float s[8][8];
#pragma unroll
    for (int i = 0; i < 8; i++)
#pragma unroll
        for (int jj = 0; jj < 8; jj++) {
            float v = lo32(acc[i][jj]) + hi32(acc[i][jj]);
            v += __shfl_xor_sync(0xffffffffu, v, 1);
            s[i][jj] = v;
        }

    // thread kc writes rows with i%2==kc; b strided (bg + 8*jj)
#pragma unroll
    for (int i = 0; i < 8; i++) {
        if ((i & 1) == kc) {
            const int row = rg * 8 + i;
            const float bias = bsrc[u0 + row];
            float* Cp = g_Gx + ((size_t)t * NG + (size_t)gate * NH + u0 + row) * NB;
#pragma unroll
            for (int jj = 0; jj < 8; jj++)
                Cp[bg + 8 * jj] = s[i][jj] + bias;
        }
    }
}

// =====================================================================
// Phase 2: persistent recurrent kernel. 128 CTAs x 256 threads.
// h stored [b][k] in global -> NO transpose. Tile copy: 16 float2 per
// thread (FULL 64x128 tile = 4096 float2), warp reads/writes 32
// consecutive float2 per row -> coalesced LDG + conflict-free STS.
// Register double-buffered. Weights SMEM-resident all 512 steps.
// 8x8 reg tile, 8-way K-split + 3-round shfl butterfly.
// =====================================================================
#define SW_STRIDE 1032
#define SH_STRIDE 130
#define SG_STRIDE 68
#define P2_SMEM ((32 * SW_STRIDE + NB * SH_STRIDE + 32 * SG_STRIDE) * 4)  // 174080 B

__device__ __forceinline__ void grid_barrier() {
    __threadfence();
    __syncthreads();
    if (threadIdx.x == 0) {
        volatile unsigned* vgen = &g_bar_gen;
        const unsigned gen = *vgen;
        const unsigned arrived = atomicAdd(&g_bar_count, 1u);
        if ((arrived & 127u) == 127u) {
            atomicAdd(&g_bar_gen, 1u);
        } else {
            while (*vgen == gen) { }
        }
    }
    __syncthreads();
    __threadfence();
}

__global__ __launch_bounds__(256, 1) void lstm_steps(
    const float* __restrict__ Wf, const float* __restrict__ Wi,
    const float* __restrict__ Wc, const float* __restrict__ Wo,
    float* __restrict__ out)
{
    extern __shared__ float smem[];
    float* sW = smem;                      // 32 x 1032   weights, whole kernel
    float* sH = sW + 32 * SW_STRIDE;       // 64 x 130    h tile [b][k]
    float* sG = sH + NB * SH_STRIDE;       // 32 x 68     staged gate pre-acts

    const int tid    = threadIdx.x;
    const int u_base = blockIdx.x * 8;

    // Load this CTA's 32 weight rows (h-part = cols [0, NH)) into SMEM once.
    for (int i = tid; i < 8192; i += 256) {       // 8192 float4s
        const int r = i >> 8, q = i & 255;
        const int g = r >> 3, ul = r & 7;
        const float* Wsrc = (g == 0) ? Wf : (g == 1) ? Wi : (g == 2) ? Wc : Wo;
        const float4 v = *reinterpret_cast<const float4*>(
            Wsrc + (size_t)(u_base + ul) * NHX + q * 4);
        *reinterpret_cast<float4*>(&sW[r * SW_STRIDE + q * 4]) = v;
    }
    // Zero h buffer 0 for owned columns (h_{-1} = 0), layout [b][k].
    for (int i = tid; i < 8 * NB; i += 256) {
        const int b = i >> 3, uc = i & 7;
        g_hbuf[0][(size_t)b * NH + u_base + uc] = 0.f;
    }

    // dot-phase mapping
    const int kc = tid & 7;                // K split slot
    const int bg = (tid >> 3) & 7;         // batches bg*8 .. bg*8+7
    const int rg = tid >> 6;               // gate; rows rg*8 .. rg*8+7
    // copy mapping: 16 float2/thread; b = cb + 4p, float2 slot ck2
    const int cb  = tid >> 6;              // 0..3
    const int ck2 = tid & 63;              // float2 slot within row (0..63)
    // combine mapping
    const int u_l = tid >> 5;
    const int bp  = tid & 31;
    const int b0  = bp * 2;
    float2 creg = make_float2(0.f, 0.f);

    grid_barrier();   // h0 zeros visible everywhere

    for (int t = 0; t < TSEQ; t++) {
        const float* hprev = g_hbuf[t & 1];
        float* hnext = g_hbuf[(t & 1) ^ 1];

        unsigned long long acc[8][8];
#pragma unroll
        for (int i = 0; i < 8; i++)
#pragma unroll
            for (int j = 0; j < 8; j++) acc[i][j] = 0ULL;

        // preload tile 0 (k in [0,128)): FULL tile = 4096 float2 = 256thr x 16
        float2 hreg[16];
#pragma unroll
        for (int p = 0; p < 16; p++) {
            const int b = cb + p * 4;
            hreg[p] = __ldcg(reinterpret_cast<const float2*>(
                hprev + (size_t)b * NH + 2 * ck2));
        }

        for (int it = 0; it < 8; it++) {
            const int kt = it * 128;
            __syncthreads();   // everyone done computing previous tile
#pragma unroll
            for (int p = 0; p < 16; p++) {
                const int b = cb + p * 4;
                *reinterpret_cast<float2*>(&sH[b * SH_STRIDE + 2 * ck2]) = hreg[p];
            }
            __syncthreads();   // tile visible
            if (it < 7) {
#pragma unroll
                for (int p = 0; p < 16; p++) {
                    const int b = cb + p * 4;
                    hreg[p] = __ldcg(reinterpret_cast<const float2*>(
                        hprev + (size_t)b * NH + kt + 128 + 2 * ck2));
                }
            }

            const float* wb = sW + rg * 8 * SW_STRIDE + kt + 2 * kc;
            const float* hb = sH + bg * 8 * SH_STRIDE + 2 * kc;
#pragma unroll 2
            for (int j = 0; j < 8; j++) {        // k-pair = 8j + kc
                unsigned long long wv[8], hv[8];
#pragma unroll
                for (int i = 0; i < 8; i++) wv[i] = lds64(wb + i * SW_STRIDE + 16 * j);
#pragma unroll
                for (int jj = 0; jj < 8; jj++) hv[jj] = lds64(hb + jj * SH_STRIDE + 16 * j);
#pragma unroll
                for (int i = 0; i < 8; i++)
#pragma unroll
                    for (int jj = 0; jj < 8; jj++)
                        fma2(acc[i][jj], wv[i], hv[jj]);
            }
        }

        // reduce halves + 3-round butterfly over kc (lane bits 0..2)
        float s[8][8];
#pragma unroll
        for (int i = 0; i < 8; i++)
#pragma unroll
            for (int jj = 0; jj < 8; jj++) {
                float v = lo32(acc[i][jj]) + hi32(acc[i][jj]);
                v += __shfl_xor_sync(0xffffffffu, v, 1);
                v += __shfl_xor_sync(0xffffffffu, v, 2);
                v += __shfl_xor_sync(0xffffffffu, v, 4);
                s[i][jj] = v;
            }

        __syncthreads();   // sG free (prev combine done)
#pragma unroll
        for (int i = 0; i < 8; i++) {
            if (i == kc) {
                float* Gr = &sG[(rg * 8 + i) * SG_STRIDE + bg * 8];
                *reinterpret_cast<float4*>(Gr) =
                    make_float4(s[i][0], s[i][1], s[i][2], s[i][3]);
                *reinterpret_cast<float4*>(Gr + 4) =
                    make_float4(s[i][4], s[i][5], s[i][6], s[i][7]);
            }
        }
        __syncthreads();

        // combine: gates -> c, h; h stored [b][k] in global
        {
            const int u = u_base + u_l;
            const float* Gp = g_Gx + (size_t)t * NG * NB;
            const float2 hf = *reinterpret_cast<const float2*>(&sG[(0  + u_l) * SG_STRIDE + b0]);
            const float2 hi = *reinterpret_cast<const float2*>(&sG[(8  + u_l) * SG_STRIDE + b0]);
            const float2 hc = *reinterpret_cast<const float2*>(&sG[(16 + u_l) * SG_STRIDE + b0]);
            const float2 ho = *reinterpret_cast<const float2*>(&sG[(24 + u_l) * SG_STRIDE + b0]);
            const float2 xf = *reinterpret_cast<const float2*>(Gp + ((size_t)0 * NH + u) * NB + b0);
            const float2 xi = *reinterpret_cast<const float2*>(Gp + ((size_t)1 * NH + u) * NB + b0);
            const float2 xc = *reinterpret_cast<const float2*>(Gp + ((size_t)2 * NH + u) * NB + b0);
            const float2 xo = *reinterpret_cast<const float2*>(Gp + ((size_t)3 * NH + u) * NB + b0);

            const float fx = sigmoidf_(hf.x + xf.x), fy = sigmoidf_(hf.y + xf.y);
            const float ix = sigmoidf_(hi.x + xi.x), iy = sigmoidf_(hi.y + xi.y);
            const float cx = tanhf(hc.x + xc.x),     cy = tanhf(hc.y + xc.y);
            const float ox = sigmoidf_(ho.x + xo.x), oy = sigmoidf_(ho.y + xo.y);

            creg.x = fx * creg.x + ix * cx;
            creg.y = fy * creg.y + iy * cy;
            const float hx_ = ox * tanhf(creg.x);
            const float hy_ = oy * tanhf(creg.y);

            __stcg(hnext + (size_t)b0 * NH + u, hx_);
            __stcg(hnext + (size_t)(b0 + 1) * NH + u, hy_);
            out[((size_t)t * NB + b0) * NH + u]     = hx_;
            out[((size_t)t * NB + b0 + 1) * NH + u] = hy_;
        }

        grid_barrier();   // h_t visible before anyone reads it at t+1
    }
}

// =====================================================================
// launch
// =====================================================================
extern "C" void kernel_launch(void* const* d_in, const int* in_sizes, int n_in,
                              void* d_out, int out_size)
{
    const float* x  = (const float*)d_in[0];
    const float* Wf = (const float*)d_in[1];
    const float* bf = (const float*)d_in[2];
    const float* Wi = (const float*)d_in[3];
    const float* bi = (const float*)d_in[4];
    const float* Wc = (const float*)d_in[5];
    const float* bc = (const float*)d_in[6];
    const float* Wo = (const float*)d_in[7];
    const float* bo = (const float*)d_in[8];
    float* out = (float*)d_out;

    (void)in_sizes; (void)n_in; (void)out_size;

    cudaFuncSetAttribute(lstm_steps, cudaFuncAttributeMaxDynamicSharedMemorySize, P2_SMEM);

    gx_gemm<<<dim3(64, TSEQ), 128>>>(x, Wf, Wi, Wc, Wo, bf, bi, bc, bo);
    lstm_steps<<<128, 256, P2_SMEM>>>(Wf, Wi, Wc, Wo, out);
}